// round 5
// baseline (speedup 1.0000x reference)
#include <cuda_runtime.h>
#include <cuda_fp16.h>
#include <cstdint>

// Fused int4-dequant + GEMM via mma.sync.m16n8k16 fp16 (base ISA; harness
// compiles through compute_103 PTX so tcgen05 is unavailable).
// R5: 64x64 warp tiles (CTA 256x128, 8 warps) to cut LDSM smem traffic from
// 3B to 2B per output per K32-iter -> smem floor drops below HMMA floor.

#define MM   8192
#define NN   4096
#define KK   4096
#define NGRP 32
#define KW   512

#define BM 256
#define BN 128
#define BK 32
#define NSTG 4
#define PITCH 40                          // halfs per smem row (64B data + 16B pad)
#define A_HALFS (BM * PITCH)              // 10240
#define B_HALFS (BN * PITCH)              // 5120
#define STAGE_HALFS (A_HALFS + B_HALFS)   // 15360 halfs = 30720 B
#define SMEM_BYTES (NSTG * STAGE_HALFS * 2)   // 122880
#define NKITER (KK / BK)                  // 128

// ---------------- device scratch ----------------
__device__ __half g_xh[(size_t)MM * KK];
__device__ __half g_wh[(size_t)NN * KK];

__device__ __forceinline__ uint32_t smem_u32(const void* p) {
    return (uint32_t)__cvta_generic_to_shared(p);
}

#define LDSM_X4(r, addr) \
    asm volatile("ldmatrix.sync.aligned.m8n8.x4.shared.b16 {%0,%1,%2,%3}, [%4];" \
                 : "=r"((r)[0]), "=r"((r)[1]), "=r"((r)[2]), "=r"((r)[3]) \
                 : "r"(addr))

#define MMA16816(c, a, b0, b1) \
    asm volatile("mma.sync.aligned.m16n8k16.row.col.f32.f16.f16.f32 " \
                 "{%0,%1,%2,%3}, {%4,%5,%6,%7}, {%8,%9}, {%0,%1,%2,%3};" \
                 : "+f"((c)[0]), "+f"((c)[1]), "+f"((c)[2]), "+f"((c)[3]) \
                 : "r"((a)[0]), "r"((a)[1]), "r"((a)[2]), "r"((a)[3]), \
                   "r"(b0), "r"(b1))

#define CP16(dst, src) \
    asm volatile("cp.async.cg.shared.global [%0], [%1], 16;" :: "r"(dst), "l"(src))

// ---------------- pass 0: round x to fp16 ----------------
__global__ void __launch_bounds__(256) round_x_kernel(const float* __restrict__ x) {
    size_t i = ((size_t)blockIdx.x * 256 + threadIdx.x) * 8;
    float4 v0 = *(const float4*)(x + i);
    float4 v1 = *(const float4*)(x + i + 4);
    float f[8] = {v0.x, v0.y, v0.z, v0.w, v1.x, v1.y, v1.z, v1.w};
    __half h[8];
#pragma unroll
    for (int j = 0; j < 8; j++) h[j] = __float2half_rn(f[j]);
    *(uint4*)(g_xh + i) = *(const uint4*)h;
}

// ---------------- pass 1: dequant int4 weights -> fp16 ----------------
__global__ void __launch_bounds__(256) dequant_kernel(const int* __restrict__ qw,
                                                      const float* __restrict__ sc,
                                                      const float* __restrict__ zp) {
    int idx = blockIdx.x * 256 + threadIdx.x;
    int n = idx >> 9;
    int w = idx & 511;
    unsigned word = ((const unsigned*)qw)[idx];
    int g = w >> 4;
    float s = sc[n * NGRP + g];
    float z = zp[n * NGRP + g];
    __half o[8];
#pragma unroll
    for (int i = 0; i < 8; i++) {
        float q = (float)((word >> (4 * i)) & 0xF);
        o[i] = __float2half_rn(s * (q - z));
    }
    *(uint4*)(g_wh + (size_t)n * KK + w * 8) = *(const uint4*)o;
}

// ---------------- pass 2: GEMM ----------------
__global__ void __launch_bounds__(256, 1)
gemm_fp16_kernel(const float* __restrict__ bias, float* __restrict__ out) {
    extern __shared__ __half sm[];
    const int tid = threadIdx.x;
    const int wid = tid >> 5;
    const int lane = tid & 31;
    const int warp_m = wid >> 1;       // 0..3 -> 64 rows each
    const int warp_n = wid & 1;        // 0..1 -> 64 cols each
    const int m0 = blockIdx.y * BM;
    const int n0 = blockIdx.x * BN;

    float acc[4][8][4];
#pragma unroll
    for (int i = 0; i < 4; i++)
#pragma unroll
        for (int j = 0; j < 8; j++)
#pragma unroll
            for (int r = 0; r < 4; r++) acc[i][j][r] = 0.f;

    // loader: A 1024 chunks + B 512 chunks of 16B; 256 threads -> 6 chunks each
    const int lrow = tid >> 2;         // 0..63
    const int lc = tid & 3;            // 0..3

    auto load_stage = [&](int s) {
        int buf = s & (NSTG - 1);
        uint32_t st = smem_u32(sm + buf * STAGE_HALFS);
        int k0 = s * BK;
        const __half* Ah = g_xh + (size_t)m0 * KK + k0;
        const __half* Bh = g_wh + (size_t)n0 * KK + k0;
#pragma unroll
        for (int i = 0; i < 4; i++) {  // A: 4 x 64 rows
            int row = lrow + i * 64;
            uint32_t doff = (uint32_t)(row * PITCH + lc * 8) * 2;
            CP16(st + doff, Ah + (size_t)row * KK + lc * 8);
        }
#pragma unroll
        for (int i = 0; i < 2; i++) {  // B: 2 x 64 rows
            int row = lrow + i * 64;
            uint32_t doff = (uint32_t)(row * PITCH + lc * 8) * 2;
            CP16(st + A_HALFS * 2 + doff, Bh + (size_t)row * KK + lc * 8);
        }
        asm volatile("cp.async.commit_group;");
    };

    load_stage(0);
    load_stage(1);
    load_stage(2);

    const int lrow16 = lane & 15;
    const int lk8 = (lane >> 4) * 8;

    for (int s = 0; s < NKITER; s++) {
        asm volatile("cp.async.wait_group 2;" ::: "memory");
        __syncthreads();

        int buf = s & (NSTG - 1);
        uint32_t sA = smem_u32(sm + buf * STAGE_HALFS);
        uint32_t sB = sA + A_HALFS * 2;

#pragma unroll
        for (int ks = 0; ks < 2; ks++) {
            uint32_t kb = (uint32_t)(ks * 16 + lk8) * 2;
            uint32_t ah[4][4], bb[4][4];
#pragma unroll
            for (int mi = 0; mi < 4; mi++) {
                uint32_t ro = (uint32_t)((warp_m * 64 + mi * 16 + lrow16) * PITCH) * 2 + kb;
                LDSM_X4(ah[mi], sA + ro);
            }
#pragma unroll
            for (int ng = 0; ng < 4; ng++) {
                uint32_t ro = (uint32_t)((warp_n * 64 + ng * 16 + lrow16) * PITCH) * 2 + kb;
                LDSM_X4(bb[ng], sB + ro);
            }
#pragma unroll
            for (int mi = 0; mi < 4; mi++) {
#pragma unroll
                for (int nj = 0; nj < 8; nj++) {
                    uint32_t b0 = bb[nj >> 1][nj & 1];
                    uint32_t b1 = bb[nj >> 1][(nj & 1) + 2];
                    MMA16816(acc[mi][nj], ah[mi], b0, b1);
                }
            }
        }
        if (s + 3 < NKITER) load_stage(s + 3);
    }

    // ---------------- epilogue ----------------
    const int rb = lane >> 2;
    const int cb = (lane & 3) * 2;
#pragma unroll
    for (int mi = 0; mi < 4; mi++) {
        int m = m0 + warp_m * 64 + mi * 16 + rb;
#pragma unroll
        for (int nj = 0; nj < 8; nj++) {
            int n = n0 + warp_n * 64 + nj * 8 + cb;
            float2 bv = *(const float2*)(bias + n);
            float2 o0, o1;
            o0.x = acc[mi][nj][0] + bv.x;
            o0.y = acc[mi][nj][1] + bv.y;
            o1.x = acc[mi][nj][2] + bv.x;
            o1.y = acc[mi][nj][3] + bv.y;
            *(float2*)(out + (size_t)m * NN + n) = o0;
            *(float2*)(out + (size_t)(m + 8) * NN + n) = o1;
        }
    }
}

// ---------------- launch ----------------
extern "C" void kernel_launch(void* const* d_in, const int* in_sizes, int n_in,
                              void* d_out, int out_size) {
    const float* x    = (const float*)d_in[0];
    const int*   qw   = (const int*)d_in[1];
    const float* sc   = (const float*)d_in[2];
    const float* zp   = (const float*)d_in[3];
    const float* bias = (const float*)d_in[4];
    float* out = (float*)d_out;

    cudaFuncSetAttribute(gemm_fp16_kernel,
                         cudaFuncAttributeMaxDynamicSharedMemorySize, SMEM_BYTES);

    round_x_kernel<<<(int)(((size_t)MM * KK) / 2048), 256>>>(x);
    dequant_kernel<<<(NN * KW) / 256, 256>>>(qw, sc, zp);
    gemm_fp16_kernel<<<dim3(NN / BN, MM / BM), 256, SMEM_BYTES>>>(bias, out);
}